// round 1
// baseline (speedup 1.0000x reference)
#include <cuda_runtime.h>
#include <cuda_bf16.h>
#include <math.h>

#define Bb   4
#define Nn   4096
#define DIMx 1024
#define Hh   16
#define Dd   64
#define Mm   128
#define DIi  1024        // H*D
#define QKVC 3072        // 3*H*D

typedef long long ll;

// ---------------- scratch (static device globals; no allocation) ----------------
__device__ float g_qkv  [(size_t)Bb * Nn * QKVC];   // 50,331,648  (q|k|v interleaved per reference reshape)
__device__ float g_a    [Hh * Mm * Dd];             // scaled agent tokens
__device__ float g_qa   [(size_t)Bb * Hh * Nn * Mm];
__device__ float g_ak   [(size_t)Bb * Hh * Mm * Nn];
__device__ float g_qa2  [(size_t)Bb * Hh * Nn * Mm];
__device__ float g_ak2  [(size_t)Bb * Hh * Mm * Nn];
__device__ float g_agent[(size_t)Bb * Hh * Mm * Dd];
__device__ float g_tmp  [(size_t)Bb * Nn * DIi];
__device__ float g_maskf[Bb * Nn];
__device__ int   g_mflag;

// ---------------- mask dtype detection + normalization ----------------
// reference mask is bool; harness dtype unknown. Detect by byte patterns over
// the first Bb*Nn bytes (safe lower bound for every candidate dtype).
__global__ void mask_detect(const void* mraw) {
    const unsigned char* p = (const unsigned char*)mraw;
    __shared__ int c_gt1, c_off, c_off1;
    if (threadIdx.x == 0) { c_gt1 = 0; c_off = 0; c_off1 = 0; }
    __syncthreads();
    int l_gt1 = 0, l_off = 0, l_off1 = 0;
    for (int i = threadIdx.x; i < Bb * Nn; i += 256) {
        unsigned char v = p[i];
        if (v > 1) l_gt1++;
        if ((i & 3) != 0 && v != 0) l_off++;
        if ((i & 3) == 1 && v != 0) l_off1++;
    }
    atomicAdd(&c_gt1, l_gt1); atomicAdd(&c_off, l_off); atomicAdd(&c_off1, l_off1);
    __syncthreads();
    if (threadIdx.x == 0) {
        int f;
        if (c_gt1 > 64)      f = (c_off1 > 64) ? 3 : 2;  // bf16 : float32
        else if (c_off > 64) f = 0;                       // bool / uint8
        else                 f = 1;                       // int32
        g_mflag = f;
    }
}

__global__ void mask_expand(const void* mraw, float* __restrict__ maskf) {
    int i = blockIdx.x * 256 + threadIdx.x;
    if (i >= Bb * Nn) return;
    int f = g_mflag;
    float v;
    if (f == 0)      v = ((const unsigned char*)mraw)[i] ? 1.f : 0.f;
    else if (f == 1) v = ((const int*)mraw)[i] ? 1.f : 0.f;
    else if (f == 2) v = (((const float*)mraw)[i] != 0.f) ? 1.f : 0.f;
    else             v = (__bfloat162float(((const __nv_bfloat16*)mraw)[i]) != 0.f) ? 1.f : 0.f;
    maskf[i] = v;
}

// ---------------- agent token prescale (SCALE = 64^-0.5 = 0.125) ----------------
__global__ void scale_agents(const float* __restrict__ at, float* __restrict__ out) {
    int i = blockIdx.x * 256 + threadIdx.x;
    if (i < Hh * Mm * Dd) out[i] = at[i] * 0.125f;
}

// ---------------- generic batched tiled SGEMM ----------------
// C[M,Ncols] = A[M,K] * B  (B row-major [K,Ncols] if !TRANSB, else [Ncols,K])
// batch z decomposed as z = zb*zdiv + zh with independent (b,h) strides.
// MASKED: multiply C row gr by rowmask[zb*M + gr] (zero masked rows).
template<bool TRANSB, bool MASKED>
__global__ __launch_bounds__(256)
void sgemm(const float* __restrict__ Ain, int lda, ll sAb, ll sAh,
           const float* __restrict__ Bin, int ldb, ll sBb, ll sBh,
           float* __restrict__ Cout, int ldc, ll sCb, ll sCh,
           int Mrows, int Ncols, int K, int zdiv,
           const float* __restrict__ rowmask)
{
    int z  = blockIdx.z;
    int zb = z / zdiv, zh = z % zdiv;
    const float* A  = Ain + zb * sAb + zh * sAh;
    const float* Bm = Bin + zb * sBb + zh * sBh;
    float*       C  = Cout + zb * sCb + zh * sCh;

    __shared__ float As[8][128];
    __shared__ float Bs[8][128];

    int tid = threadIdx.x;
    int tx = tid & 15, ty = tid >> 4;
    int bm = blockIdx.y * 128, bn = blockIdx.x * 128;

    int lr = tid >> 1;         // 0..127
    int lc = (tid & 1) * 4;    // 0 or 4

    float acc[8][8];
#pragma unroll
    for (int i = 0; i < 8; i++)
#pragma unroll
        for (int j = 0; j < 8; j++) acc[i][j] = 0.f;

    for (int k0 = 0; k0 < K; k0 += 8) {
        {   // A tile 128x8 -> As[k][m]
            float4 v = make_float4(0.f, 0.f, 0.f, 0.f);
            int gr = bm + lr;
            if (gr < Mrows) v = *reinterpret_cast<const float4*>(A + (ll)gr * lda + k0 + lc);
            As[lc + 0][lr] = v.x; As[lc + 1][lr] = v.y;
            As[lc + 2][lr] = v.z; As[lc + 3][lr] = v.w;
        }
        if (TRANSB) {   // B tile [Ncols,K] slice 128x8 -> Bs[k][n]
            float4 v = make_float4(0.f, 0.f, 0.f, 0.f);
            int gn = bn + lr;
            if (gn < Ncols) v = *reinterpret_cast<const float4*>(Bm + (ll)gn * ldb + k0 + lc);
            Bs[lc + 0][lr] = v.x; Bs[lc + 1][lr] = v.y;
            Bs[lc + 2][lr] = v.z; Bs[lc + 3][lr] = v.w;
        } else {        // B tile 8x128 -> Bs[k][n]
            int br = tid >> 5;           // 0..7
            int bc = (tid & 31) * 4;     // 0..124
            float4 v = make_float4(0.f, 0.f, 0.f, 0.f);
            int gn = bn + bc;
            if (gn < Ncols) v = *reinterpret_cast<const float4*>(Bm + (ll)(k0 + br) * ldb + gn);
            *reinterpret_cast<float4*>(&Bs[br][bc]) = v;
        }
        __syncthreads();
#pragma unroll
        for (int kk = 0; kk < 8; kk++) {
            float ar[8], br_[8];
#pragma unroll
            for (int i = 0; i < 8; i++) ar[i]  = As[kk][ty * 8 + i];
#pragma unroll
            for (int j = 0; j < 8; j++) br_[j] = Bs[kk][tx * 8 + j];
#pragma unroll
            for (int i = 0; i < 8; i++)
#pragma unroll
                for (int j = 0; j < 8; j++)
                    acc[i][j] = fmaf(ar[i], br_[j], acc[i][j]);
        }
        __syncthreads();
    }

#pragma unroll
    for (int i = 0; i < 8; i++) {
        int gr = bm + ty * 8 + i;
        if (gr >= Mrows) continue;
        float mv = 1.f;
        if (MASKED) mv = rowmask[(ll)zb * Mrows + gr];
#pragma unroll
        for (int j = 0; j < 8; j++) {
            int gc = bn + tx * 8 + j;
            if (gc < Ncols) C[(ll)gr * ldc + gc] = acc[i][j] * mv;
        }
    }
}

// ---------------- softmax over last dim = 128 (qa_attn) ----------------
__global__ void softmax_rows128(float* __restrict__ t) {
    ll row = blockIdx.x;
    float* p = t + row * 128;
    int tid = threadIdx.x;
    float v = p[tid];
    __shared__ float red[4], red2[4];
    float m = v;
#pragma unroll
    for (int o = 16; o > 0; o >>= 1) m = fmaxf(m, __shfl_xor_sync(0xffffffffu, m, o));
    if ((tid & 31) == 0) red[tid >> 5] = m;
    __syncthreads();
    m = fmaxf(fmaxf(red[0], red[1]), fmaxf(red[2], red[3]));
    float e = expf(v - m);
    float s = e;
#pragma unroll
    for (int o = 16; o > 0; o >>= 1) s += __shfl_xor_sync(0xffffffffu, s, o);
    if ((tid & 31) == 0) red2[tid >> 5] = s;
    __syncthreads();
    s = red2[0] + red2[1] + red2[2] + red2[3];
    p[tid] = e / s;
}

// ---------------- masked softmax over last dim = 4096 (ak_attn) ----------------
__global__ void softmax_ak(float* __restrict__ t, const float* __restrict__ maskf) {
    int row = blockIdx.x;                  // (b*H + h)*M + m
    int b = row / (Hh * Mm);
    const float* mk = maskf + (ll)b * Nn;
    float* p = t + (ll)row * Nn;
    int tid = threadIdx.x;                 // 256
    float vals[16];
    float mx = -3.402823466e38f;
#pragma unroll
    for (int i = 0; i < 16; i++) {
        int n = tid + i * 256;
        float raw = p[n];
        float x = (mk[n] > 0.5f) ? raw : -3.402823466e38f;
        vals[i] = x;
        mx = fmaxf(mx, x);
    }
    __shared__ float red[8], red2[8];
#pragma unroll
    for (int o = 16; o > 0; o >>= 1) mx = fmaxf(mx, __shfl_xor_sync(0xffffffffu, mx, o));
    if ((tid & 31) == 0) red[tid >> 5] = mx;
    __syncthreads();
    mx = red[0];
#pragma unroll
    for (int w = 1; w < 8; w++) mx = fmaxf(mx, red[w]);
    float s = 0.f;
#pragma unroll
    for (int i = 0; i < 16; i++) { vals[i] = expf(vals[i] - mx); s += vals[i]; }
#pragma unroll
    for (int o = 16; o > 0; o >>= 1) s += __shfl_xor_sync(0xffffffffu, s, o);
    if ((tid & 31) == 0) red2[tid >> 5] = s;
    __syncthreads();
    s = 0.f;
#pragma unroll
    for (int w = 0; w < 8; w++) s += red2[w];
    float inv = 1.f / s;
#pragma unroll
    for (int i = 0; i < 16; i++) p[tid + i * 256] = vals[i] * inv;
}

// ---------------- talking heads: dst[b,g,x] = sum_h W[g,h] * src[b,h,x] ----------------
__global__ void talking_heads(const float* __restrict__ src, float* __restrict__ dst,
                              const float* __restrict__ W) {
    __shared__ float Ws[16][16];
    int tid = threadIdx.x;
    if (tid < 256) Ws[tid >> 4][tid & 15] = W[tid];
    __syncthreads();
    const ll X = (ll)Nn * Mm;                       // 524288
    ll idx = (ll)blockIdx.x * blockDim.x + tid;     // over B*X
    if (idx >= (ll)Bb * X) return;
    int b = (int)(idx / X);
    ll  x = idx % X;
    const float* sp = src + ((ll)b * Hh) * X + x;
    float sv[16];
#pragma unroll
    for (int h = 0; h < 16; h++) sv[h] = sp[(ll)h * X];
    float* dp = dst + ((ll)b * Hh) * X + x;
#pragma unroll
    for (int g = 0; g < 16; g++) {
        float acc = 0.f;
#pragma unroll
        for (int h = 0; h < 16; h++) acc = fmaf(Ws[g][h], sv[h], acc);
        dp[(ll)g * X] = acc;
    }
}

// ---------------- launch ----------------
extern "C" void kernel_launch(void* const* d_in, const int* in_sizes, int n_in,
                              void* d_out, int out_size) {
    (void)in_sizes; (void)n_in; (void)out_size;
    const float* x      = (const float*)d_in[0];
    const void*  mask   = d_in[1];
    const float* Wqkv   = (const float*)d_in[2];
    const float* agents = (const float*)d_in[3];
    const float* Wqa    = (const float*)d_in[4];
    const float* Wak    = (const float*)d_in[5];
    const float* Wout   = (const float*)d_in[6];
    float* out = (float*)d_out;

    float *qkv, *a, *qa, *ak, *qa2, *ak2, *agent, *tmp, *maskf;
    cudaGetSymbolAddress((void**)&qkv,   g_qkv);
    cudaGetSymbolAddress((void**)&a,     g_a);
    cudaGetSymbolAddress((void**)&qa,    g_qa);
    cudaGetSymbolAddress((void**)&ak,    g_ak);
    cudaGetSymbolAddress((void**)&qa2,   g_qa2);
    cudaGetSymbolAddress((void**)&ak2,   g_ak2);
    cudaGetSymbolAddress((void**)&agent, g_agent);
    cudaGetSymbolAddress((void**)&tmp,   g_tmp);
    cudaGetSymbolAddress((void**)&maskf, g_maskf);

    mask_detect<<<1, 256>>>(mask);
    mask_expand<<<(Bb * Nn + 255) / 256, 256>>>(mask, maskf);
    scale_agents<<<(Hh * Mm * Dd + 255) / 256, 256>>>(agents, a);

    // K1: qkv = x @ W_qkv   [16384,1024]@[1024,3072]
    sgemm<false, false><<<dim3(QKVC / 128, (Bb * Nn) / 128, 1), 256>>>(
        x, DIMx, 0, 0,
        Wqkv, QKVC, 0, 0,
        qkv, QKVC, 0, 0,
        Bb * Nn, QKVC, DIMx, 1, nullptr);

    // K2: qa_sim[b,h,n,m] = q[b,h] (ld 3072, col-off h*64) @ a[h]^T   NT
    sgemm<true, false><<<dim3(1, Nn / 128, Bb * Hh), 256>>>(
        qkv, QKVC, (ll)Nn * QKVC, 64,
        a, Dd, 0, (ll)Mm * Dd,
        qa, Mm, (ll)Hh * Nn * Mm, (ll)Nn * Mm,
        Nn, Mm, Dd, Hh, nullptr);

    softmax_rows128<<<Bb * Hh * Nn, 128>>>(qa);

    // K3: ak_sim[b,h,m,n] = a[h] @ k[b,h]^T   NT  (k at col-offset 1024)
    sgemm<true, false><<<dim3(Nn / 128, 1, Bb * Hh), 256>>>(
        a, Dd, 0, (ll)Mm * Dd,
        qkv + DIi, QKVC, (ll)Nn * QKVC, 64,
        ak, Nn, (ll)Hh * Mm * Nn, (ll)Mm * Nn,
        Mm, Nn, Dd, Hh, nullptr);

    softmax_ak<<<Bb * Hh * Mm, 256>>>(ak, maskf);

    talking_heads<<<(Bb * Nn * Mm) / 256, 256>>>(qa, qa2, Wqa);
    talking_heads<<<(Bb * Nn * Mm) / 256, 256>>>(ak, ak2, Wak);

    // K5: agent_out[b,h,m,d] = ak2[b,h] @ v[b,h]   NN  (v at col-offset 2048)
    sgemm<false, false><<<dim3(1, 1, Bb * Hh), 256>>>(
        ak2, Nn, (ll)Hh * Mm * Nn, (ll)Mm * Nn,
        qkv + 2 * DIi, QKVC, (ll)Nn * QKVC, 64,
        agent, Dd, (ll)Hh * Mm * Dd, (ll)Mm * Dd,
        Mm, Dd, Nn, Hh, nullptr);

    // K6: out[b,h,n,d] = qa2[b,h] @ agent[b,h], masked, scattered into tmp[b,n,h*64+d]
    sgemm<false, true><<<dim3(1, Nn / 128, Bb * Hh), 256>>>(
        qa2, Mm, (ll)Hh * Nn * Mm, (ll)Nn * Mm,
        agent, Dd, (ll)Hh * Mm * Dd, (ll)Mm * Dd,
        tmp, DIi, (ll)Nn * DIi, 64,
        Nn, Dd, Mm, Hh, maskf);

    // K7: out = tmp @ W_out   [16384,1024]@[1024,1024]
    sgemm<false, false><<<dim3(DIMx / 128, (Bb * Nn) / 128, 1), 256>>>(
        tmp, DIi, 0, 0,
        Wout, DIMx, 0, 0,
        out, DIMx, 0, 0,
        Bb * Nn, DIMx, DIi, 1, nullptr);
}

// round 3
// speedup vs baseline: 2.0781x; 2.0781x over previous
#include <cuda_runtime.h>
#include <cuda_bf16.h>
#include <math.h>
#include <stdint.h>

#define Bb   4
#define Nn   4096
#define DIMx 1024
#define Hh   16
#define Dd   64
#define Mm   128
#define DIi  1024        // H*D
#define QKVC 3072        // 3*H*D

typedef long long ll;

// ---------------- scratch (static device globals; no allocation) ----------------
__device__ float g_qkv  [(size_t)Bb * Nn * QKVC];
__device__ float g_a    [Hh * Mm * Dd];
__device__ float g_qa   [(size_t)Bb * Hh * Nn * Mm];
__device__ float g_ak   [(size_t)Bb * Hh * Mm * Nn];
__device__ float g_qa2  [(size_t)Bb * Hh * Nn * Mm];
__device__ float g_ak2  [(size_t)Bb * Hh * Mm * Nn];
__device__ float g_agent[(size_t)Bb * Hh * Mm * Dd];
__device__ float g_tmp  [(size_t)Bb * Nn * DIi];
__device__ float g_maskf[Bb * Nn];
__device__ float g_WqkvT[(size_t)QKVC * DIMx];
__device__ float g_WoutT[(size_t)DIMx * DIi];
__device__ int   g_mflag;

// ---------------- helpers ----------------
__device__ __forceinline__ uint32_t f2tf(float x) {
    uint32_t r; asm("cvt.rna.tf32.f32 %0, %1;" : "=r"(r) : "f"(x)); return r;
}
__device__ __forceinline__ void mma1688(float c[4], const uint32_t a[4], const uint32_t b[2]) {
    asm volatile(
        "mma.sync.aligned.m16n8k8.row.col.f32.tf32.tf32.f32 "
        "{%0,%1,%2,%3}, {%4,%5,%6,%7}, {%8,%9}, {%0,%1,%2,%3};"
        : "+f"(c[0]), "+f"(c[1]), "+f"(c[2]), "+f"(c[3])
        : "r"(a[0]), "r"(a[1]), "r"(a[2]), "r"(a[3]), "r"(b[0]), "r"(b[1]));
}

// ================= tf32 mma.sync GEMM =================
// C[M,N] = A[M,K] @ Bt[N,K]^T  (both K-major), batched via blockIdx.z.
// Tiles: CTA 128x128, warp 32x64, K-chunk 32. M,N multiples of 128; K multiple of 32.
#define SMS   36                 // smem row stride (floats), conflict-free frag loads
#define ABUF  (128 * SMS)        // one operand tile (floats)
#define BUFSZ (2 * ABUF)         // A+B tile (floats)
#define GMMA_SMEM (2 * BUFSZ * 4)  // 73728 bytes

__global__ __launch_bounds__(256, 1)
void gemm_mma(const float* __restrict__ Ain, int lda, ll sAb, ll sAh,
              const float* __restrict__ Btin, int ldb, ll sBb, ll sBh,
              float* __restrict__ Cout, int ldc, ll sCb, ll sCh,
              int K, int zdiv)
{
    extern __shared__ float sm[];
    int z = blockIdx.z, zb = z / zdiv, zh = z % zdiv;
    const float* A  = Ain  + zb * sAb + zh * sAh;
    const float* Bt = Btin + zb * sBb + zh * sBh;
    float*       C  = Cout + zb * sCb + zh * sCh;

    int tid = threadIdx.x, lane = tid & 31, wid = tid >> 5;
    int bm = blockIdx.y * 128, bn = blockIdx.x * 128;
    int wm = (wid & 3) * 32, wn = (wid >> 2) * 64;
    int g = lane >> 2, tc = lane & 3;

    float cfr[2][8][4];
#pragma unroll
    for (int i = 0; i < 2; i++)
#pragma unroll
        for (int j = 0; j < 8; j++)
#pragma unroll
            for (int q = 0; q < 4; q++) cfr[i][j][q] = 0.f;

    const int fr = tid >> 3;          // 0..31 : row group
    const int fc = (tid & 7) * 4;     // 0..28 : col within 32-float chunk

    float4 av[4], bv[4];
    // prologue: load chunk 0
#pragma unroll
    for (int i = 0; i < 4; i++)
        av[i] = *reinterpret_cast<const float4*>(A + (ll)(bm + fr + i * 32) * lda + fc);
#pragma unroll
    for (int i = 0; i < 4; i++)
        bv[i] = *reinterpret_cast<const float4*>(Bt + (ll)(bn + fr + i * 32) * ldb + fc);
    {
        float* dA = sm;            // buffer 0
        float* dB = sm + ABUF;
#pragma unroll
        for (int i = 0; i < 4; i++) {
            float4 o;
            o.x = __uint_as_float(f2tf(av[i].x)); o.y = __uint_as_float(f2tf(av[i].y));
            o.z = __uint_as_float(f2tf(av[i].z)); o.w = __uint_as_float(f2tf(av[i].w));
            *reinterpret_cast<float4*>(dA + (fr + i * 32) * SMS + fc) = o;
            float4 p;
            p.x = __uint_as_float(f2tf(bv[i].x)); p.y = __uint_as_float(f2tf(bv[i].y));
            p.z = __uint_as_float(f2tf(bv[i].z)); p.w = __uint_as_float(f2tf(bv[i].w));
            *reinterpret_cast<float4*>(dB + (fr + i * 32) * SMS + fc) = p;
        }
    }
    __syncthreads();

    const int NC = K / 32;
    for (int c = 0; c < NC; c++) {
        const float* curA = sm + (c & 1) * BUFSZ;
        const float* curB = curA + ABUF;
        if (c + 1 < NC) {
            int k0 = (c + 1) * 32;
#pragma unroll
            for (int i = 0; i < 4; i++)
                av[i] = *reinterpret_cast<const float4*>(A + (ll)(bm + fr + i * 32) * lda + k0 + fc);
#pragma unroll
            for (int i = 0; i < 4; i++)
                bv[i] = *reinterpret_cast<const float4*>(Bt + (ll)(bn + fr + i * 32) * ldb + k0 + fc);
        }
#pragma unroll
        for (int k8 = 0; k8 < 4; k8++) {
            int k0 = k8 * 8;
            uint32_t afr[2][4];
#pragma unroll
            for (int i = 0; i < 2; i++) {
                const float* pa = curA + (wm + i * 16 + g) * SMS + k0 + tc;
                afr[i][0] = __float_as_uint(pa[0]);
                afr[i][1] = __float_as_uint(pa[8 * SMS]);
                afr[i][2] = __float_as_uint(pa[4]);
                afr[i][3] = __float_as_uint(pa[8 * SMS + 4]);
            }
            uint32_t bfr[8][2];
#pragma unroll
            for (int j = 0; j < 8; j++) {
                const float* pb = curB + (wn + j * 8 + g) * SMS + k0 + tc;
                bfr[j][0] = __float_as_uint(pb[0]);
                bfr[j][1] = __float_as_uint(pb[4]);
            }
#pragma unroll
            for (int i = 0; i < 2; i++)
#pragma unroll
                for (int j = 0; j < 8; j++)
                    mma1688(cfr[i][j], afr[i], bfr[j]);
        }
        if (c + 1 < NC) {
            float* dA = sm + ((c + 1) & 1) * BUFSZ;
            float* dB = dA + ABUF;
#pragma unroll
            for (int i = 0; i < 4; i++) {
                float4 o;
                o.x = __uint_as_float(f2tf(av[i].x)); o.y = __uint_as_float(f2tf(av[i].y));
                o.z = __uint_as_float(f2tf(av[i].z)); o.w = __uint_as_float(f2tf(av[i].w));
                *reinterpret_cast<float4*>(dA + (fr + i * 32) * SMS + fc) = o;
                float4 p;
                p.x = __uint_as_float(f2tf(bv[i].x)); p.y = __uint_as_float(f2tf(bv[i].y));
                p.z = __uint_as_float(f2tf(bv[i].z)); p.w = __uint_as_float(f2tf(bv[i].w));
                *reinterpret_cast<float4*>(dB + (fr + i * 32) * SMS + fc) = p;
            }
        }
        __syncthreads();
    }

    // epilogue
#pragma unroll
    for (int i = 0; i < 2; i++) {
        int row = bm + wm + i * 16 + g;
#pragma unroll
        for (int j = 0; j < 8; j++) {
            int col = bn + wn + j * 8 + 2 * tc;
            float2 v0 = make_float2(cfr[i][j][0], cfr[i][j][1]);
            float2 v1 = make_float2(cfr[i][j][2], cfr[i][j][3]);
            *reinterpret_cast<float2*>(C + (ll)row * ldc + col) = v0;
            *reinterpret_cast<float2*>(C + (ll)(row + 8) * ldc + col) = v1;
        }
    }
}

// ---------------- transpose: out[c][r] = in[r][c] ----------------
__global__ void transpose_k(const float* __restrict__ in, float* __restrict__ out,
                            int rows, int cols) {
    __shared__ float t[32][33];
    int bx = blockIdx.x * 32, by = blockIdx.y * 32;
    int x = bx + threadIdx.x;
#pragma unroll
    for (int i = 0; i < 32; i += 8) {
        int y = by + threadIdx.y + i;
        if (x < cols && y < rows) t[threadIdx.y + i][threadIdx.x] = in[(ll)y * cols + x];
    }
    __syncthreads();
    x = by + threadIdx.x;
#pragma unroll
    for (int i = 0; i < 32; i += 8) {
        int y = bx + threadIdx.y + i;
        if (x < rows && y < cols) out[(ll)y * rows + x] = t[threadIdx.x][threadIdx.y + i];
    }
}

// ---------------- mask dtype detection + normalization ----------------
__global__ void mask_detect(const void* mraw) {
    const unsigned char* p = (const unsigned char*)mraw;
    __shared__ int c_gt1, c_off, c_off1;
    if (threadIdx.x == 0) { c_gt1 = 0; c_off = 0; c_off1 = 0; }
    __syncthreads();
    int l_gt1 = 0, l_off = 0, l_off1 = 0;
    for (int i = threadIdx.x; i < Bb * Nn; i += 256) {
        unsigned char v = p[i];
        if (v > 1) l_gt1++;
        if ((i & 3) != 0 && v != 0) l_off++;
        if ((i & 3) == 1 && v != 0) l_off1++;
    }
    atomicAdd(&c_gt1, l_gt1); atomicAdd(&c_off, l_off); atomicAdd(&c_off1, l_off1);
    __syncthreads();
    if (threadIdx.x == 0) {
        int f;
        if (c_gt1 > 64)      f = (c_off1 > 64) ? 3 : 2;
        else if (c_off > 64) f = 0;
        else                 f = 1;
        g_mflag = f;
    }
}

__global__ void mask_expand(const void* mraw, float* __restrict__ maskf) {
    int i = blockIdx.x * 256 + threadIdx.x;
    if (i >= Bb * Nn) return;
    int f = g_mflag;
    float v;
    if (f == 0)      v = ((const unsigned char*)mraw)[i] ? 1.f : 0.f;
    else if (f == 1) v = ((const int*)mraw)[i] ? 1.f : 0.f;
    else if (f == 2) v = (((const float*)mraw)[i] != 0.f) ? 1.f : 0.f;
    else             v = (__bfloat162float(((const __nv_bfloat16*)mraw)[i]) != 0.f) ? 1.f : 0.f;
    maskf[i] = v;
}

__global__ void scale_agents(const float* __restrict__ at, float* __restrict__ out) {
    int i = blockIdx.x * 256 + threadIdx.x;
    if (i < Hh * Mm * Dd) out[i] = at[i] * 0.125f;
}

// ---------------- generic batched tiled SGEMM (small GEMMs K5/K6) ----------------
template<bool TRANSB, bool MASKED>
__global__ __launch_bounds__(256)
void sgemm(const float* __restrict__ Ain, int lda, ll sAb, ll sAh,
           const float* __restrict__ Bin, int ldb, ll sBb, ll sBh,
           float* __restrict__ Cout, int ldc, ll sCb, ll sCh,
           int Mrows, int Ncols, int K, int zdiv,
           const float* __restrict__ rowmask)
{
    int z  = blockIdx.z;
    int zb = z / zdiv, zh = z % zdiv;
    const float* A  = Ain + zb * sAb + zh * sAh;
    const float* Bm = Bin + zb * sBb + zh * sBh;
    float*       C  = Cout + zb * sCb + zh * sCh;

    __shared__ float As[8][128];
    __shared__ float Bs[8][128];

    int tid = threadIdx.x;
    int tx = tid & 15, ty = tid >> 4;
    int bm = blockIdx.y * 128, bn = blockIdx.x * 128;

    int lr = tid >> 1;
    int lc = (tid & 1) * 4;

    float acc[8][8];
#pragma unroll
    for (int i = 0; i < 8; i++)
#pragma unroll
        for (int j = 0; j < 8; j++) acc[i][j] = 0.f;

    for (int k0 = 0; k0 < K; k0 += 8) {
        {
            float4 v = make_float4(0.f, 0.f, 0.f, 0.f);
            int gr = bm + lr;
            if (gr < Mrows) v = *reinterpret_cast<const float4*>(A + (ll)gr * lda + k0 + lc);
            As[lc + 0][lr] = v.x; As[lc + 1][lr] = v.y;
            As[lc + 2][lr] = v.z; As[lc + 3][lr] = v.w;
        }
        if (TRANSB) {
            float4 v = make_float4(0.f, 0.f, 0.f, 0.f);
            int gn = bn + lr;
            if (gn < Ncols) v = *reinterpret_cast<const float4*>(Bm + (ll)gn * ldb + k0 + lc);
            Bs[lc + 0][lr] = v.x; Bs[lc + 1][lr] = v.y;
            Bs[lc + 2][lr] = v.z; Bs[lc + 3][lr] = v.w;
        } else {
            int br = tid >> 5;
            int bc = (tid & 31) * 4;
            float4 v = make_float4(0.f, 0.f, 0.f, 0.f);
            int gn = bn + bc;
            if (gn < Ncols) v = *reinterpret_cast<const float4*>(Bm + (ll)(k0 + br) * ldb + gn);
            *reinterpret_cast<float4*>(&Bs[br][bc]) = v;
        }
        __syncthreads();
#pragma unroll
        for (int kk = 0; kk < 8; kk++) {
            float ar[8], br_[8];
#pragma unroll
            for (int i = 0; i < 8; i++) ar[i]  = As[kk][ty * 8 + i];
#pragma unroll
            for (int j = 0; j < 8; j++) br_[j] = Bs[kk][tx * 8 + j];
#pragma unroll
            for (int i = 0; i < 8; i++)
#pragma unroll
                for (int j = 0; j < 8; j++)
                    acc[i][j] = fmaf(ar[i], br_[j], acc[i][j]);
        }
        __syncthreads();
    }

#pragma unroll
    for (int i = 0; i < 8; i++) {
        int gr = bm + ty * 8 + i;
        if (gr >= Mrows) continue;
        float mv = 1.f;
        if (MASKED) mv = rowmask[(ll)zb * Mrows + gr];
#pragma unroll
        for (int j = 0; j < 8; j++) {
            int gc = bn + tx * 8 + j;
            if (gc < Ncols) C[(ll)gr * ldc + gc] = acc[i][j] * mv;
        }
    }
}

// ---------------- softmax over last dim = 128 ----------------
__global__ void softmax_rows128(float* __restrict__ t) {
    ll row = blockIdx.x;
    float* p = t + row * 128;
    int tid = threadIdx.x;
    float v = p[tid];
    __shared__ float red[4], red2[4];
    float m = v;
#pragma unroll
    for (int o = 16; o > 0; o >>= 1) m = fmaxf(m, __shfl_xor_sync(0xffffffffu, m, o));
    if ((tid & 31) == 0) red[tid >> 5] = m;
    __syncthreads();
    m = fmaxf(fmaxf(red[0], red[1]), fmaxf(red[2], red[3]));
    float e = expf(v - m);
    float s = e;
#pragma unroll
    for (int o = 16; o > 0; o >>= 1) s += __shfl_xor_sync(0xffffffffu, s, o);
    if ((tid & 31) == 0) red2[tid >> 5] = s;
    __syncthreads();
    s = red2[0] + red2[1] + red2[2] + red2[3];
    p[tid] = e / s;
}

// ---------------- masked softmax over last dim = 4096 ----------------
__global__ void softmax_ak(float* __restrict__ t, const float* __restrict__ maskf) {
    int row = blockIdx.x;
    int b = row / (Hh * Mm);
    const float* mk = maskf + (ll)b * Nn;
    float* p = t + (ll)row * Nn;
    int tid = threadIdx.x;
    float vals[16];
    float mx = -3.402823466e38f;
#pragma unroll
    for (int i = 0; i < 16; i++) {
        int n = tid + i * 256;
        float raw = p[n];
        float x = (mk[n] > 0.5f) ? raw : -3.402823466e38f;
        vals[i] = x;
        mx = fmaxf(mx, x);
    }
    __shared__ float red[8], red2[8];
#pragma unroll
    for (int o = 16; o > 0; o >>= 1) mx = fmaxf(mx, __shfl_xor_sync(0xffffffffu, mx, o));
    if ((tid & 31) == 0) red[tid >> 5] = mx;
    __syncthreads();
    mx = red[0];
#pragma unroll
    for (int w = 1; w < 8; w++) mx = fmaxf(mx, red[w]);
    float s = 0.f;
#pragma unroll
    for (int i = 0; i < 16; i++) { vals[i] = expf(vals[i] - mx); s += vals[i]; }
#pragma unroll
    for (int o = 16; o > 0; o >>= 1) s += __shfl_xor_sync(0xffffffffu, s, o);
    if ((tid & 31) == 0) red2[tid >> 5] = s;
    __syncthreads();
    s = 0.f;
#pragma unroll
    for (int w = 0; w < 8; w++) s += red2[w];
    float inv = 1.f / s;
#pragma unroll
    for (int i = 0; i < 16; i++) p[tid + i * 256] = vals[i] * inv;
}

// ---------------- talking heads ----------------
__global__ void talking_heads(const float* __restrict__ src, float* __restrict__ dst,
                              const float* __restrict__ W) {
    __shared__ float Ws[16][16];
    int tid = threadIdx.x;
    if (tid < 256) Ws[tid >> 4][tid & 15] = W[tid];
    __syncthreads();
    const ll X = (ll)Nn * Mm;
    ll idx = (ll)blockIdx.x * blockDim.x + tid;
    if (idx >= (ll)Bb * X) return;
    int b = (int)(idx / X);
    ll  x = idx % X;
    const float* sp = src + ((ll)b * Hh) * X + x;
    float sv[16];
#pragma unroll
    for (int h = 0; h < 16; h++) sv[h] = sp[(ll)h * X];
    float* dp = dst + ((ll)b * Hh) * X + x;
#pragma unroll
    for (int g = 0; g < 16; g++) {
        float acc = 0.f;
#pragma unroll
        for (int h = 0; h < 16; h++) acc = fmaf(Ws[g][h], sv[h], acc);
        dp[(ll)g * X] = acc;
    }
}

// ---------------- launch ----------------
extern "C" void kernel_launch(void* const* d_in, const int* in_sizes, int n_in,
                              void* d_out, int out_size) {
    (void)in_sizes; (void)n_in; (void)out_size;
    const float* x      = (const float*)d_in[0];
    const void*  mask   = d_in[1];
    const float* Wqkv   = (const float*)d_in[2];
    const float* agents = (const float*)d_in[3];
    const float* Wqa    = (const float*)d_in[4];
    const float* Wak    = (const float*)d_in[5];
    const float* Wout   = (const float*)d_in[6];
    float* out = (float*)d_out;

    float *qkv, *a, *qa, *ak, *qa2, *ak2, *agent, *tmp, *maskf, *WqkvT, *WoutT;
    cudaGetSymbolAddress((void**)&qkv,   g_qkv);
    cudaGetSymbolAddress((void**)&a,     g_a);
    cudaGetSymbolAddress((void**)&qa,    g_qa);
    cudaGetSymbolAddress((void**)&ak,    g_ak);
    cudaGetSymbolAddress((void**)&qa2,   g_qa2);
    cudaGetSymbolAddress((void**)&ak2,   g_ak2);
    cudaGetSymbolAddress((void**)&agent, g_agent);
    cudaGetSymbolAddress((void**)&tmp,   g_tmp);
    cudaGetSymbolAddress((void**)&maskf, g_maskf);
    cudaGetSymbolAddress((void**)&WqkvT, g_WqkvT);
    cudaGetSymbolAddress((void**)&WoutT, g_WoutT);

    static int smem_set = 0;
    if (!smem_set) {
        cudaFuncSetAttribute(gemm_mma, cudaFuncAttributeMaxDynamicSharedMemorySize, GMMA_SMEM);
        smem_set = 1;
    }

    mask_detect<<<1, 256>>>(mask);
    mask_expand<<<(Bb * Nn + 255) / 256, 256>>>(mask, maskf);
    scale_agents<<<(Hh * Mm * Dd + 255) / 256, 256>>>(agents, a);

    // transposed weights for K-major B operands
    transpose_k<<<dim3(QKVC / 32, DIMx / 32), dim3(32, 8)>>>(Wqkv, WqkvT, DIMx, QKVC);
    transpose_k<<<dim3(DIMx / 32, DIi / 32), dim3(32, 8)>>>(Wout, WoutT, DIi, DIMx);

    // K1: qkv = x @ W_qkv    [16384,1024]@[1024,3072]  (tf32 mma)
    gemm_mma<<<dim3(QKVC / 128, (Bb * Nn) / 128, 1), 256, GMMA_SMEM>>>(
        x, DIMx, 0, 0,
        WqkvT, DIMx, 0, 0,
        qkv, QKVC, 0, 0,
        DIMx, 1);

    // K2: qa_sim[b,h,n,m] = q[b,h] @ a[h]^T   (tf32 mma; A=q view, Bt=a)
    gemm_mma<<<dim3(Mm / 128, Nn / 128, Bb * Hh), 256, GMMA_SMEM>>>(
        qkv, QKVC, (ll)Nn * QKVC, 64,
        a, Dd, 0, (ll)Mm * Dd,
        qa, Mm, (ll)Hh * Nn * Mm, (ll)Nn * Mm,
        Dd, Hh);

    softmax_rows128<<<Bb * Hh * Nn, 128>>>(qa);

    // K3: ak_sim[b,h,m,n] = a[h] @ k[b,h]^T   (tf32 mma; Bt=k view)
    gemm_mma<<<dim3(Nn / 128, Mm / 128, Bb * Hh), 256, GMMA_SMEM>>>(
        a, Dd, 0, (ll)Mm * Dd,
        qkv + DIi, QKVC, (ll)Nn * QKVC, 64,
        ak, Nn, (ll)Hh * Mm * Nn, (ll)Mm * Nn,
        Dd, Hh);

    softmax_ak<<<Bb * Hh * Mm, 256>>>(ak, maskf);

    talking_heads<<<(Bb * Nn * Mm) / 256, 256>>>(qa, qa2, Wqa);
    talking_heads<<<(Bb * Nn * Mm) / 256, 256>>>(ak, ak2, Wak);

    // K5: agent_out[b,h,m,d] = ak2[b,h] @ v[b,h]   NN (SIMT; N=64)
    sgemm<false, false><<<dim3(1, 1, Bb * Hh), 256>>>(
        ak2, Nn, (ll)Hh * Mm * Nn, (ll)Mm * Nn,
        qkv + 2 * DIi, QKVC, (ll)Nn * QKVC, 64,
        agent, Dd, (ll)Hh * Mm * Dd, (ll)Mm * Dd,
        Mm, Dd, Nn, Hh, nullptr);

    // K6: out[b,h,n,d] = qa2[b,h] @ agent[b,h], masked, scattered into tmp
    sgemm<false, true><<<dim3(1, Nn / 128, Bb * Hh), 256>>>(
        qa2, Mm, (ll)Hh * Nn * Mm, (ll)Nn * Mm,
        agent, Dd, (ll)Hh * Mm * Dd, (ll)Mm * Dd,
        tmp, DIi, (ll)Nn * DIi, 64,
        Nn, Dd, Mm, Hh, maskf);

    // K7: out = tmp @ W_out   [16384,1024]@[1024,1024]  (tf32 mma)
    gemm_mma<<<dim3(DIMx / 128, (Bb * Nn) / 128, 1), 256, GMMA_SMEM>>>(
        tmp, DIi, 0, 0,
        WoutT, DIi, 0, 0,
        out, DIMx, 0, 0,
        DIi, 1);
}

// round 5
// speedup vs baseline: 3.6899x; 1.7757x over previous
#include <cuda_runtime.h>
#include <cuda_bf16.h>
#include <math.h>
#include <stdint.h>

#define Bb   4
#define Nn   4096
#define DIMx 1024
#define Hh   16
#define Dd   64
#define Mm   128
#define DIi  1024        // H*D
#define QKVC 3072        // 3*H*D

typedef long long ll;

// ---------------- scratch ----------------
__device__ float g_qkv  [(size_t)Bb * Nn * QKVC];
__device__ float g_xc   [(size_t)Bb * Nn * DIMx];
__device__ float g_a    [Hh * Mm * Dd];
__device__ float g_qa   [(size_t)Bb * Hh * Nn * Mm];
__device__ float g_ak   [(size_t)Bb * Hh * Mm * Nn];
__device__ float g_qa2  [(size_t)Bb * Hh * Nn * Mm];
__device__ float g_ak2  [(size_t)Bb * Hh * Mm * Nn];
__device__ float g_vt   [(size_t)Bb * Hh * Dd * Nn];
__device__ float g_agT  [Bb * Hh * Dd * Mm];
__device__ float g_tmp  [(size_t)Bb * Nn * DIi];
__device__ float g_maskf[Bb * Nn];
__device__ float g_WqkvT[(size_t)QKVC * DIMx];
__device__ float g_WoutT[(size_t)DIMx * DIi];
__device__ int   g_mflag;

// ---------------- helpers ----------------
__device__ __forceinline__ uint32_t smem_u32(const void* p) {
    uint32_t a;
    asm("{ .reg .u64 t; cvta.to.shared.u64 t, %1; cvt.u32.u64 %0, t; }" : "=r"(a) : "l"(p));
    return a;
}
__device__ __forceinline__ uint32_t f2tf(float x) {
    uint32_t r; asm("cvt.rna.tf32.f32 %0, %1;" : "=r"(r) : "f"(x)); return r;
}
__device__ __forceinline__ float tfr(float x) { return __uint_as_float(f2tf(x)); }
__device__ __forceinline__ void cp16(uint32_t saddr, const void* gaddr) {
    asm volatile("cp.async.cg.shared.global [%0], [%1], 16;" :: "r"(saddr), "l"(gaddr));
}
__device__ __forceinline__ void cp_commit() { asm volatile("cp.async.commit_group;"); }
__device__ __forceinline__ void cp_wait1()  { asm volatile("cp.async.wait_group 1;" ::: "memory"); }
__device__ __forceinline__ void mma1688(float c[4], const uint32_t a[4], const uint32_t b[2]) {
    asm volatile(
        "mma.sync.aligned.m16n8k8.row.col.f32.tf32.tf32.f32 "
        "{%0,%1,%2,%3}, {%4,%5,%6,%7}, {%8,%9}, {%0,%1,%2,%3};"
        : "+f"(c[0]), "+f"(c[1]), "+f"(c[2]), "+f"(c[3])
        : "r"(a[0]), "r"(a[1]), "r"(a[2]), "r"(a[3]), "r"(b[0]), "r"(b[1]));
}

// ================= templated tf32 mma.sync GEMM =================
// C[M,N] = A[M,K] @ Bt[N,K]^T, both K-major, operands pre-rounded to tf32.
// 8 warps; (BM/WM)*(BN/WN) must be 8. K-chunk 32, 3-stage cp.async.
#define SMS 36

template<int BM, int BN, int WM, int WN, bool MASKED, bool TFOUT>
__global__ void __launch_bounds__(256, 1)
gemm_mma(const float* __restrict__ Ain, int lda, ll sAb, ll sAh,
         const float* __restrict__ Btin, int ldb, ll sBb, ll sBh,
         float* __restrict__ Cout, int ldc, ll sCb, ll sCh,
         int K, int zdiv, const float* __restrict__ rowmask, int mstride)
{
    constexpr int MI = WM / 16, NJ = WN / 8;
    constexpr int WROWS = BM / WM;
    constexpr int AST = BM * SMS, STG = (BM + BN) * SMS;
    extern __shared__ float sm[];
    uint32_t smb = smem_u32(sm);

    int z = blockIdx.z, zb = z / zdiv, zh = z % zdiv;
    const float* A  = Ain  + zb * sAb + zh * sAh;
    const float* Bt = Btin + zb * sBb + zh * sBh;
    float*       C  = Cout + zb * sCb + zh * sCh;

    int tid = threadIdx.x, lane = tid & 31, wid = tid >> 5;
    int bm = blockIdx.y * BM, bn = blockIdx.x * BN;
    int wm = (wid % WROWS) * WM, wn = (wid / WROWS) * WN;
    int g = lane >> 2, tc = lane & 3;

    float cfr[MI][NJ][4];
#pragma unroll
    for (int i = 0; i < MI; i++)
#pragma unroll
        for (int j = 0; j < NJ; j++)
#pragma unroll
            for (int q = 0; q < 4; q++) cfr[i][j][q] = 0.f;

    const int r = tid >> 3, c4 = (tid & 7) * 4;
    const int NC = K / 32;

    auto load_stage = [&](int s, int kk) {
        uint32_t dst = smb + (uint32_t)(s * STG) * 4;
#pragma unroll
        for (int i = 0; i < BM / 32; i++)
            cp16(dst + ((r + i * 32) * SMS + c4) * 4,
                 A + (ll)(bm + r + i * 32) * lda + kk + c4);
        uint32_t dstB = dst + AST * 4;
#pragma unroll
        for (int i = 0; i < BN / 32; i++)
            cp16(dstB + ((r + i * 32) * SMS + c4) * 4,
                 Bt + (ll)(bn + r + i * 32) * ldb + kk + c4);
    };

    load_stage(0, 0);
    cp_commit();
    if (1 < NC) load_stage(1, 32);
    cp_commit();

    for (int c = 0; c < NC; c++) {
        cp_wait1();
        __syncthreads();
        int pf = c + 2;
        if (pf < NC) load_stage(pf % 3, pf * 32);
        cp_commit();

        const float* cA = sm + (c % 3) * STG;
        const float* cB = cA + AST;
#pragma unroll
        for (int k8 = 0; k8 < 4; k8++) {
            int k0 = k8 * 8;
            uint32_t afr[MI][4];
#pragma unroll
            for (int i = 0; i < MI; i++) {
                const float* pa = cA + (wm + i * 16 + g) * SMS + k0 + tc;
                afr[i][0] = __float_as_uint(pa[0]);
                afr[i][1] = __float_as_uint(pa[8 * SMS]);
                afr[i][2] = __float_as_uint(pa[4]);
                afr[i][3] = __float_as_uint(pa[8 * SMS + 4]);
            }
            uint32_t bfr[NJ][2];
#pragma unroll
            for (int j = 0; j < NJ; j++) {
                const float* pb = cB + (wn + j * 8 + g) * SMS + k0 + tc;
                bfr[j][0] = __float_as_uint(pb[0]);
                bfr[j][1] = __float_as_uint(pb[4]);
            }
#pragma unroll
            for (int i = 0; i < MI; i++)
#pragma unroll
                for (int j = 0; j < NJ; j++)
                    mma1688(cfr[i][j], afr[i], bfr[j]);
        }
    }

    // epilogue
#pragma unroll
    for (int i = 0; i < MI; i++) {
        int row = bm + wm + i * 16 + g;
        float m0 = 1.f, m1 = 1.f;
        if (MASKED) {
            m0 = rowmask[(ll)zb * mstride + row];
            m1 = rowmask[(ll)zb * mstride + row + 8];
        }
#pragma unroll
        for (int j = 0; j < NJ; j++) {
            int col = bn + wn + j * 8 + 2 * tc;
            float2 v0, v1;
            v0.x = cfr[i][j][0] * m0; v0.y = cfr[i][j][1] * m0;
            v1.x = cfr[i][j][2] * m1; v1.y = cfr[i][j][3] * m1;
            if (TFOUT) { v0.x = tfr(v0.x); v0.y = tfr(v0.y); v1.x = tfr(v1.x); v1.y = tfr(v1.y); }
            *reinterpret_cast<float2*>(C + (ll)row * ldc + col) = v0;
            *reinterpret_cast<float2*>(C + (ll)(row + 8) * ldc + col) = v1;
        }
    }
}

// ---------------- weight transpose (rounds to tf32) ----------------
__global__ void transpose_k(const float* __restrict__ in, float* __restrict__ out,
                            int rows, int cols) {
    __shared__ float t[32][33];
    int bx = blockIdx.x * 32, by = blockIdx.y * 32;
    int x = bx + threadIdx.x;
#pragma unroll
    for (int i = 0; i < 32; i += 8) {
        int y = by + threadIdx.y + i;
        if (x < cols && y < rows) t[threadIdx.y + i][threadIdx.x] = in[(ll)y * cols + x];
    }
    __syncthreads();
    x = by + threadIdx.x;
#pragma unroll
    for (int i = 0; i < 32; i += 8) {
        int y = bx + threadIdx.y + i;
        if (x < rows && y < cols) out[(ll)y * rows + x] = tfr(t[threadIdx.x][threadIdx.y + i]);
    }
}

// ---------------- v transpose: vt[b,h][d][n] from qkv v-view (already tf32) ----------------
__global__ void transpose_v(const float* __restrict__ qkv, float* __restrict__ vt) {
    __shared__ float t[32][33];
    int zz = blockIdx.z;                        // b*16+h
    const float* src = qkv + (ll)(zz >> 4) * Nn * QKVC + 2048 + (zz & 15) * 64;
    int n0 = blockIdx.x * 32, d0 = blockIdx.y * 32;
#pragma unroll
    for (int i = 0; i < 32; i += 8)
        t[threadIdx.y + i][threadIdx.x] = src[(ll)(n0 + threadIdx.y + i) * QKVC + d0 + threadIdx.x];
    __syncthreads();
    float* dst = vt + ((ll)zz * Dd) * Nn;
#pragma unroll
    for (int i = 0; i < 32; i += 8)
        dst[(ll)(d0 + threadIdx.y + i) * Nn + n0 + threadIdx.x] = t[threadIdx.x][threadIdx.y + i];
}

// ---------------- x -> tf32-rounded copy ----------------
__global__ void convert_x(const float* __restrict__ in, float* __restrict__ out, int n4) {
    int i = blockIdx.x * 256 + threadIdx.x;
    if (i >= n4) return;
    float4 v = reinterpret_cast<const float4*>(in)[i];
    v.x = tfr(v.x); v.y = tfr(v.y); v.z = tfr(v.z); v.w = tfr(v.w);
    reinterpret_cast<float4*>(out)[i] = v;
}

// ---------------- mask detect/expand ----------------
__global__ void mask_detect(const void* mraw) {
    const unsigned char* p = (const unsigned char*)mraw;
    __shared__ int c_gt1, c_off, c_off1;
    if (threadIdx.x == 0) { c_gt1 = 0; c_off = 0; c_off1 = 0; }
    __syncthreads();
    int l_gt1 = 0, l_off = 0, l_off1 = 0;
    for (int i = threadIdx.x; i < Bb * Nn; i += 256) {
        unsigned char v = p[i];
        if (v > 1) l_gt1++;
        if ((i & 3) != 0 && v != 0) l_off++;
        if ((i & 3) == 1 && v != 0) l_off1++;
    }
    atomicAdd(&c_gt1, l_gt1); atomicAdd(&c_off, l_off); atomicAdd(&c_off1, l_off1);
    __syncthreads();
    if (threadIdx.x == 0) {
        int f;
        if (c_gt1 > 64)      f = (c_off1 > 64) ? 3 : 2;
        else if (c_off > 64) f = 0;
        else                 f = 1;
        g_mflag = f;
    }
}

__global__ void mask_expand(const void* mraw, float* __restrict__ maskf) {
    int i = blockIdx.x * 256 + threadIdx.x;
    if (i >= Bb * Nn) return;
    int f = g_mflag;
    float v;
    if (f == 0)      v = ((const unsigned char*)mraw)[i] ? 1.f : 0.f;
    else if (f == 1) v = ((const int*)mraw)[i] ? 1.f : 0.f;
    else if (f == 2) v = (((const float*)mraw)[i] != 0.f) ? 1.f : 0.f;
    else             v = (__bfloat162float(((const __nv_bfloat16*)mraw)[i]) != 0.f) ? 1.f : 0.f;
    maskf[i] = v;
}

__global__ void scale_agents(const float* __restrict__ at, float* __restrict__ out) {
    int i = blockIdx.x * 256 + threadIdx.x;
    if (i < Hh * Mm * Dd) out[i] = tfr(at[i] * 0.125f);
}

// ---------------- fused softmax(128) + qa talking-heads ----------------
__global__ __launch_bounds__(128)
void qa_fused(const float* __restrict__ qa, float* __restrict__ qa2,
              const float* __restrict__ Wqa) {
    int bn_ = blockIdx.x;
    int b = bn_ >> 12, n = bn_ & 4095;
    int m = threadIdx.x, lane = m & 31, warp = m >> 5;
    __shared__ float Ws[256];
    __shared__ float rb[16][4];
    Ws[m] = Wqa[m]; Ws[m + 128] = Wqa[m + 128];

    const ll hs = (ll)Nn * Mm;
    const float* base = qa + ((ll)b * Hh) * hs + (ll)n * Mm + m;
    float v[16];
#pragma unroll
    for (int h = 0; h < 16; h++) v[h] = base[(ll)h * hs];

#pragma unroll
    for (int h = 0; h < 16; h++) {
        float x = v[h];
#pragma unroll
        for (int o = 16; o > 0; o >>= 1) x = fmaxf(x, __shfl_xor_sync(0xffffffffu, x, o));
        if (lane == 0) rb[h][warp] = x;
    }
    __syncthreads();
    float p[16];
#pragma unroll
    for (int h = 0; h < 16; h++) {
        float mx = fmaxf(fmaxf(rb[h][0], rb[h][1]), fmaxf(rb[h][2], rb[h][3]));
        p[h] = __expf(v[h] - mx);
    }
    __syncthreads();
#pragma unroll
    for (int h = 0; h < 16; h++) {
        float x = p[h];
#pragma unroll
        for (int o = 16; o > 0; o >>= 1) x += __shfl_xor_sync(0xffffffffu, x, o);
        if (lane == 0) rb[h][warp] = x;
    }
    __syncthreads();
#pragma unroll
    for (int h = 0; h < 16; h++) {
        float s = rb[h][0] + rb[h][1] + rb[h][2] + rb[h][3];
        p[h] *= (1.f / s);
    }
    float* obase = qa2 + ((ll)b * Hh) * hs + (ll)n * Mm + m;
#pragma unroll
    for (int gg = 0; gg < 16; gg++) {
        float acc = 0.f;
#pragma unroll
        for (int h = 0; h < 16; h++) acc = fmaf(Ws[gg * 16 + h], p[h], acc);
        obase[(ll)gg * hs] = tfr(acc);
    }
}

// ---------------- masked softmax over last dim = 4096 (in place) ----------------
__global__ void softmax_ak(float* __restrict__ t, const float* __restrict__ maskf) {
    int row = blockIdx.x;
    int b = row / (Hh * Mm);
    const float* mk = maskf + (ll)b * Nn;
    float* p = t + (ll)row * Nn;
    int tid = threadIdx.x;
    float vals[16];
    float mx = -3.402823466e38f;
#pragma unroll
    for (int i = 0; i < 16; i++) {
        int n = tid + i * 256;
        float raw = p[n];
        float x = (mk[n] > 0.5f) ? raw : -3.402823466e38f;
        vals[i] = x;
        mx = fmaxf(mx, x);
    }
    __shared__ float red[8], red2[8];
#pragma unroll
    for (int o = 16; o > 0; o >>= 1) mx = fmaxf(mx, __shfl_xor_sync(0xffffffffu, mx, o));
    if ((tid & 31) == 0) red[tid >> 5] = mx;
    __syncthreads();
    mx = red[0];
#pragma unroll
    for (int w = 1; w < 8; w++) mx = fmaxf(mx, red[w]);
    float s = 0.f;
#pragma unroll
    for (int i = 0; i < 16; i++) { vals[i] = __expf(vals[i] - mx); s += vals[i]; }
#pragma unroll
    for (int o = 16; o > 0; o >>= 1) s += __shfl_xor_sync(0xffffffffu, s, o);
    if ((tid & 31) == 0) red2[tid >> 5] = s;
    __syncthreads();
    s = 0.f;
#pragma unroll
    for (int w = 0; w < 8; w++) s += red2[w];
    float inv = 1.f / s;
#pragma unroll
    for (int i = 0; i < 16; i++) p[tid + i * 256] = vals[i] * inv;
}

// ---------------- ak talking heads: dst[b,g,x] = round(Σ_h W[g,h] src[b,h,x]) ----------------
__global__ void talking_heads_ak(const float* __restrict__ src, float* __restrict__ dst,
                                 const float* __restrict__ W) {
    __shared__ float Ws[256];
    int tid = threadIdx.x;
    Ws[tid] = W[tid & 255];
    __syncthreads();
    const ll X = (ll)Mm * Nn;                       // per-head plane
    ll idx = (ll)blockIdx.x * blockDim.x + tid;     // over B*X
    if (idx >= (ll)Bb * X) return;
    int b = (int)(idx / X);
    ll  x = idx % X;
    const float* sp = src + ((ll)b * Hh) * X + x;
    float sv[16];
#pragma unroll
    for (int h = 0; h < 16; h++) sv[h] = sp[(ll)h * X];
    float* dp = dst + ((ll)b * Hh) * X + x;
#pragma unroll
    for (int gg = 0; gg < 16; gg++) {
        float acc = 0.f;
#pragma unroll
        for (int h = 0; h < 16; h++) acc = fmaf(Ws[gg * 16 + h], sv[h], acc);
        dp[(ll)gg * X] = tfr(acc);
    }
}

// ---------------- launch ----------------
extern "C" void kernel_launch(void* const* d_in, const int* in_sizes, int n_in,
                              void* d_out, int out_size) {
    (void)in_sizes; (void)n_in; (void)out_size;
    const float* x      = (const float*)d_in[0];
    const void*  mask   = d_in[1];
    const float* Wqkv   = (const float*)d_in[2];
    const float* agents = (const float*)d_in[3];
    const float* Wqa    = (const float*)d_in[4];
    const float* Wak    = (const float*)d_in[5];
    const float* Wout   = (const float*)d_in[6];
    float* out = (float*)d_out;

    float *qkv, *xc, *a, *qa, *ak, *qa2, *ak2, *vt, *agT, *tmp, *maskf, *WqkvT, *WoutT;
    cudaGetSymbolAddress((void**)&qkv,   g_qkv);
    cudaGetSymbolAddress((void**)&xc,    g_xc);
    cudaGetSymbolAddress((void**)&a,     g_a);
    cudaGetSymbolAddress((void**)&qa,    g_qa);
    cudaGetSymbolAddress((void**)&ak,    g_ak);
    cudaGetSymbolAddress((void**)&qa2,   g_qa2);
    cudaGetSymbolAddress((void**)&ak2,   g_ak2);
    cudaGetSymbolAddress((void**)&vt,    g_vt);
    cudaGetSymbolAddress((void**)&agT,   g_agT);
    cudaGetSymbolAddress((void**)&tmp,   g_tmp);
    cudaGetSymbolAddress((void**)&maskf, g_maskf);
    cudaGetSymbolAddress((void**)&WqkvT, g_WqkvT);
    cudaGetSymbolAddress((void**)&WoutT, g_WoutT);

    auto GBig  = gemm_mma<128, 256, 64, 64, false, true >;   // K1 (tf32 out)
    auto GBig2 = gemm_mma<128, 256, 64, 64, false, false>;   // K3, K7
    auto GMed  = gemm_mma<128, 128, 32, 64, false, false>;   // K2
    auto GAg   = gemm_mma< 64, 128, 32, 32, false, true >;   // K5': agT = vt @ ak2^T
    auto GSmM  = gemm_mma<128,  64, 32, 32, true,  true >;   // K6

    const int SM_BIG = 3 * (128 + 256) * SMS * 4;
    const int SM_MED = 3 * (128 + 128) * SMS * 4;
    const int SM_AG  = 3 * ( 64 + 128) * SMS * 4;
    const int SM_SML = 3 * (128 +  64) * SMS * 4;

    static int smem_set = 0;
    if (!smem_set) {
        cudaFuncSetAttribute(GBig,  cudaFuncAttributeMaxDynamicSharedMemorySize, SM_BIG);
        cudaFuncSetAttribute(GBig2, cudaFuncAttributeMaxDynamicSharedMemorySize, SM_BIG);
        cudaFuncSetAttribute(GMed,  cudaFuncAttributeMaxDynamicSharedMemorySize, SM_MED);
        cudaFuncSetAttribute(GAg,   cudaFuncAttributeMaxDynamicSharedMemorySize, SM_AG);
        cudaFuncSetAttribute(GSmM,  cudaFuncAttributeMaxDynamicSharedMemorySize, SM_SML);
        smem_set = 1;
    }

    mask_detect<<<1, 256>>>(mask);
    mask_expand<<<(Bb * Nn + 255) / 256, 256>>>(mask, maskf);
    scale_agents<<<(Hh * Mm * Dd + 255) / 256, 256>>>(agents, a);
    convert_x<<<(Bb * Nn * DIMx / 4 + 255) / 256, 256>>>(x, xc, Bb * Nn * DIMx / 4);
    transpose_k<<<dim3(QKVC / 32, DIMx / 32), dim3(32, 8)>>>(Wqkv, WqkvT, DIMx, QKVC);
    transpose_k<<<dim3(DIMx / 32, DIi / 32), dim3(32, 8)>>>(Wout, WoutT, DIi, DIMx);

    // K1: qkv = xc @ WqkvT^T  (tf32 out for downstream mma)
    GBig<<<dim3(QKVC / 256, (Bb * Nn) / 128, 1), 256, SM_BIG>>>(
        xc, DIMx, 0, 0,  WqkvT, DIMx, 0, 0,  qkv, QKVC, 0, 0,
        DIMx, 1, nullptr, 0);

    transpose_v<<<dim3(Nn / 32, Dd / 32, Bb * Hh), dim3(32, 8)>>>(qkv, vt);

    // K2: qa[b,h][n][m] = q @ a^T  (K=64)
    GMed<<<dim3(1, Nn / 128, Bb * Hh), 256, SM_MED>>>(
        qkv, QKVC, (ll)Nn * QKVC, 64,
        a, Dd, 0, (ll)Mm * Dd,
        qa, Mm, (ll)Hh * Nn * Mm, (ll)Nn * Mm,
        Dd, Hh, nullptr, 0);

    // K3: ak[b,h][m][n] = a @ k^T  (K=64)
    GBig2<<<dim3(Nn / 256, 1, Bb * Hh), 256, SM_BIG>>>(
        a, Dd, 0, (ll)Mm * Dd,
        qkv + DIi, QKVC, (ll)Nn * QKVC, 64,
        ak, Nn, (ll)Hh * Mm * Nn, (ll)Mm * Nn,
        Dd, Hh, nullptr, 0);

    qa_fused<<<Bb * Nn, 128>>>(qa, qa2, Wqa);
    softmax_ak<<<Bb * Hh * Mm, 256>>>(ak, maskf);
    talking_heads_ak<<<(int)(((ll)Bb * Mm * Nn + 255) / 256), 256>>>(ak, ak2, Wak);

    // K5': agT[b,g][d][m] = vt[b,g] @ ak2[b,g]^T  (K=4096, tf32 out)
    GAg<<<dim3(1, 1, Bb * Hh), 256, SM_AG>>>(
        vt, Nn, (ll)Hh * Dd * Nn, (ll)Dd * Nn,
        ak2, Nn, (ll)Hh * Mm * Nn, (ll)Mm * Nn,
        agT, Mm, (ll)Hh * Dd * Mm, (ll)Dd * Mm,
        Nn, Hh, nullptr, 0);

    // K6: tmp[b][n][g*64+d] = qa2[b,g] @ agT[b,g]^T, masked rows (K=128)
    GSmM<<<dim3(1, Nn / 128, Bb * Hh), 256, SM_SML>>>(
        qa2, Mm, (ll)Hh * Nn * Mm, (ll)Nn * Mm,
        agT, Mm, (ll)Hh * Dd * Mm, (ll)Dd * Mm,
        tmp, DIi, (ll)Nn * DIi, 64,
        Mm, Hh, maskf, Nn);

    // K7: out = tmp @ WoutT^T  (K=1024)
    GBig2<<<dim3(DIMx / 256, (Bb * Nn) / 128, 1), 256, SM_BIG>>>(
        tmp, DIi, 0, 0,  WoutT, DIi, 0, 0,  out, DIMx, 0, 0,
        DIi, 1, nullptr, 0);
}